// round 16
// baseline (speedup 1.0000x reference)
#include <cuda_runtime.h>
#include <cuda_fp16.h>
#include <math.h>
#include <stdint.h>

#define DMODEL 1024
#define NHEADS 8
#define DK 128
#define BB 2
#define SS 2048
#define NZ (BB * NHEADS)          // 16
#define NTILE (SS / 128)          // 16

// Scratch (allocation-free rule: __device__ globals)
__device__ __half g_q[(size_t)BB * SS * DMODEL];
__device__ __half g_k[(size_t)BB * SS * DMODEL];
__device__ __half g_v[(size_t)BB * SS * DMODEL];
__device__ __half g_vt[(size_t)BB * NHEADS * DK * SS];
__device__ __half g_ctx[(size_t)BB * SS * DMODEL];
__device__ float  g_attn_fb[(size_t)NZ * SS * SS];      // attn fallback only
__device__ float  g_statsM[(size_t)NZ * SS * NTILE];
__device__ float  g_statsS[(size_t)NZ * SS * NTILE];
__device__ float  g_rowM[(size_t)NZ * SS];
__device__ float  g_rowInv[(size_t)NZ * SS];
__device__ __half g_w[4][(size_t)DMODEL * DMODEL];
__device__ __half g_in[3][(size_t)BB * SS * DMODEL];

__device__ __forceinline__ uint32_t smem_u32(const void* p) {
    uint32_t a;
    asm("{ .reg .u64 t; cvta.to.shared.u64 t, %1; cvt.u32.u64 %0, t; }" : "=r"(a) : "l"(p));
    return a;
}
__device__ __forceinline__ void mma_fp16(float* c, const uint32_t* a, const uint32_t* b) {
    asm volatile(
        "mma.sync.aligned.m16n8k16.row.col.f32.f16.f16.f32 "
        "{%0,%1,%2,%3},{%4,%5,%6,%7},{%8,%9},{%0,%1,%2,%3};"
        : "+f"(c[0]), "+f"(c[1]), "+f"(c[2]), "+f"(c[3])
        : "r"(a[0]), "r"(a[1]), "r"(a[2]), "r"(a[3]), "r"(b[0]), "r"(b[1]));
}
__device__ __forceinline__ void ldmatrix_x4(uint32_t* r, uint32_t addr) {
    asm volatile("ldmatrix.sync.aligned.m8n8.x4.shared.b16 {%0,%1,%2,%3}, [%4];"
                 : "=r"(r[0]), "=r"(r[1]), "=r"(r[2]), "=r"(r[3]) : "r"(addr));
}
__device__ __forceinline__ void cp_async16(uint32_t saddr, const void* gaddr) {
    asm volatile("cp.async.cg.shared.global [%0], [%1], 16;"
                 :: "r"(saddr), "l"(gaddr) : "memory");
}
#define CP_COMMIT() asm volatile("cp.async.commit_group;" ::: "memory")
#define CP_WAIT1()  asm volatile("cp.async.wait_group 1;" ::: "memory")

__device__ __forceinline__ uint32_t pack_h2(float lo, float hi) {
    __half2 h = __floats2half2_rn(lo, hi);
    return *reinterpret_cast<uint32_t*>(&h);
}
__device__ __forceinline__ void stcs_f2(float* p, float x, float y) {
    asm volatile("st.global.cs.v2.f32 [%0], {%1, %2};" :: "l"(p), "f"(x), "f"(y) : "memory");
}

// smem word index for (row m, k-word k) within a [rows x 32-half] sub-tile.
#define SW_WORD(m, k) ((uint32_t)(m) * 16u + ((uint32_t)(k) ^ (((((uint32_t)(m)) >> 1) & 3u) << 2)))

#define STAGE_BYTES 16384u        // A(8KB) + B(8KB) per 32-half stage
#define GEMM_SMEM_BYTES 98304u    // 6 stages = 3 pair-groups

// fused attention smem layout
#define FA_Q_OFF  0u              // 4 sub-tiles (dk)      32KB
#define FA_P_OFF  32768u          // 4 sub-tiles (s-local) 32KB
#define FA_KV_OFF 65536u          // stage b: k 32KB + vt 32KB
#define FA_KV_STAGE 65536u
#define FA_SMEM_BYTES (65536u + 2u * FA_KV_STAGE)   // 196608

// ldmatrix address prep for 8-warp GEMM kernels (warp tile 64x32, mi 0..3)
#define LDM_PREP()                                                              \
    uint32_t aBaseW[4], aXorW[4];                                               \
    _Pragma("unroll")                                                           \
    for (int mi = 0; mi < 4; mi++) {                                            \
        const int rowa = warp_m * 64 + mi * 16 + (lane & 7) + ((lane >> 3) & 1) * 8; \
        aBaseW[mi] = (uint32_t)rowa * 16u;                                      \
        aXorW[mi]  = (((uint32_t)rowa >> 1) & 3u) << 2;                         \
    }                                                                           \
    const uint32_t aKsel = ((uint32_t)lane >> 4) * 4u;                          \
    uint32_t bBaseW[2], bXorW[2];                                               \
    _Pragma("unroll")                                                           \
    for (int p = 0; p < 2; p++) {                                               \
        const int rowb = warp_n * 32 + p * 16 + (lane & 7) + ((lane >> 4) & 1) * 8; \
        bBaseW[p] = (uint32_t)rowb * 16u;                                       \
        bXorW[p]  = (((uint32_t)rowb >> 1) & 3u) << 2;                          \
    }                                                                           \
    const uint32_t bKsel = (((uint32_t)lane >> 3) & 1u) * 4u;

// 2 x k16 mma steps over one 32-half sub-tile pair (mi extent 4)
#define COMPUTE_FP16(accN, abufAddr, bbufAddr)                                  \
    {                                                                           \
        _Pragma("unroll")                                                       \
        for (int ks = 0; ks < 2; ks++) {                                        \
            const uint32_t kb = ks * 8;                                         \
            uint32_t af[4][4], bf[2][4];                                        \
            _Pragma("unroll")                                                   \
            for (int mi = 0; mi < 4; mi++) {                                    \
                const uint32_t kw = kb + aKsel;                                 \
                ldmatrix_x4(af[mi], (abufAddr) + (aBaseW[mi] + (kw ^ aXorW[mi])) * 4u); \
            }                                                                   \
            _Pragma("unroll")                                                   \
            for (int p = 0; p < 2; p++) {                                       \
                const uint32_t kw = kb + bKsel;                                 \
                ldmatrix_x4(bf[p], (bbufAddr) + (bBaseW[p] + (kw ^ bXorW[p])) * 4u); \
            }                                                                   \
            _Pragma("unroll")                                                   \
            for (int mi = 0; mi < 4; mi++)                                      \
                _Pragma("unroll")                                               \
                for (int nj = 0; nj < 4; nj++)                                  \
                    mma_fp16(accN[mi][nj], af[mi], &bf[nj >> 1][(nj & 1) * 2]); \
        }                                                                       \
    }

// mi-extent-2 variant for the 16-warp flash kernel (warp tile 32x32)
#define COMPUTE_FP16_MI2(accN, abufAddr, bbufAddr)                              \
    {                                                                           \
        _Pragma("unroll")                                                       \
        for (int ks = 0; ks < 2; ks++) {                                        \
            const uint32_t kb = ks * 8;                                         \
            uint32_t af[2][4], bf[2][4];                                        \
            _Pragma("unroll")                                                   \
            for (int mi = 0; mi < 2; mi++) {                                    \
                const uint32_t kw = kb + aKsel;                                 \
                ldmatrix_x4(af[mi], (abufAddr) + (aBaseW[mi] + (kw ^ aXorW[mi])) * 4u); \
            }                                                                   \
            _Pragma("unroll")                                                   \
            for (int p = 0; p < 2; p++) {                                       \
                const uint32_t kw = kb + bKsel;                                 \
                ldmatrix_x4(bf[p], (bbufAddr) + (bBaseW[p] + (kw ^ bXorW[p])) * 4u); \
            }                                                                   \
            _Pragma("unroll")                                                   \
            for (int mi = 0; mi < 2; mi++)                                      \
                _Pragma("unroll")                                               \
                for (int nj = 0; nj < 4; nj++)                                  \
                    mma_fp16(accN[mi][nj], af[mi], &bf[nj >> 1][(nj & 1) * 2]); \
        }                                                                       \
    }

// ============================================================================
// Batched FP16 GEMM, pair-grouped cp.async pipeline. 256 threads, 2 CTA/SM.
//   C = alpha * A @ B^T + bias.  WRITE_C=false: stats-only.  K%64==0, K>=128.
// ============================================================================
template <bool HAS_BIAS, bool STATS, bool OUT_HALF, bool WRITE_C>
__global__ __launch_bounds__(256, 2) void gemm_fp16_kernel(
    const __half* __restrict__ A, const __half* __restrict__ B,
    const float* __restrict__ bias, void* __restrict__ Cv,
    int K, int lda, int ldb, int ldc, float alpha,
    int Hdiv,
    long long sAb, long long sAh,
    long long sBb, long long sBh,
    long long sCb, long long sCh,
    float* __restrict__ statsM, float* __restrict__ statsS)
{
    extern __shared__ char smem[];
    const uint32_t sb = smem_u32(smem);

    const int z  = blockIdx.z;
    const int zb = z / Hdiv;
    const int zh = z % Hdiv;
    A += zb * sAb + zh * sAh;
    B += zb * sBb + zh * sBh;
    const long long coff = zb * sCb + zh * sCh;

    const int tid  = threadIdx.x;
    const int wid  = tid >> 5;
    const int lane = tid & 31;
    const int m0   = blockIdx.y * 128;
    const int n0   = blockIdx.x * 128;
    const int warp_m = wid >> 2;
    const int warp_n = wid & 3;
    const int grp  = lane >> 2;
    const int tig  = lane & 3;

    const int lm  = tid >> 2;
    const int lcw = (tid & 3) * 4;
    const int lch = (tid & 3) * 8;

    LDM_PREP()

    float acc[4][4][4];
#pragma unroll
    for (int i = 0; i < 4; i++)
#pragma unroll
        for (int j = 0; j < 4; j++)
#pragma unroll
            for (int q = 0; q < 4; q++) acc[i][j][q] = 0.0f;

#define ISSUE_BODY(bufi, k0)                                                    \
    {                                                                           \
        const uint32_t ab = sb + (uint32_t)(bufi) * STAGE_BYTES;                \
        const uint32_t bbs = ab + 8192u;                                        \
        _Pragma("unroll")                                                       \
        for (int i = 0; i < 2; i++) {                                           \
            const int m = lm + i * 64;                                          \
            cp_async16(ab + SW_WORD(m, lcw) * 4u,                               \
                       A + (long long)(m0 + m) * lda + (k0) + lch);             \
            cp_async16(bbs + SW_WORD(m, lcw) * 4u,                              \
                       B + (long long)(n0 + m) * ldb + (k0) + lch);             \
        }                                                                       \
    }

    const int G = K >> 6;   // pair-groups of 64 halves

    ISSUE_BODY(0, 0)
    ISSUE_BODY(1, 32)
    CP_COMMIT();
    ISSUE_BODY(2, 64)
    ISSUE_BODY(3, 96)
    CP_COMMIT();

    for (int g = 0; g < G; g++) {
        CP_WAIT1();
        __syncthreads();
        const int pb = (g % 3) * 2;
        {
            const uint32_t a0 = sb + (uint32_t)pb * STAGE_BYTES;
            COMPUTE_FP16(acc, a0, a0 + 8192u)
            const uint32_t a1 = a0 + STAGE_BYTES;
            COMPUTE_FP16(acc, a1, a1 + 8192u)
        }
        if (g + 2 < G) {
            const int tb = ((g + 2) % 3) * 2;
            ISSUE_BODY(tb,     (g + 2) * 64)
            ISSUE_BODY(tb + 1, (g + 2) * 64 + 32)
        }
        CP_COMMIT();
    }

    if (WRITE_C) {
#pragma unroll
        for (int nj = 0; nj < 4; nj++) {
            const int cc = n0 + warp_n * 32 + nj * 8 + tig * 2;
            float b0 = 0.0f, b1 = 0.0f;
            if (HAS_BIAS) { b0 = bias[cc]; b1 = bias[cc + 1]; }
#pragma unroll
            for (int mi = 0; mi < 4; mi++) {
                const long long r0 = m0 + warp_m * 64 + mi * 16 + grp;
                const long long r1 = r0 + 8;
                const float x0 = alpha * acc[mi][nj][0] + b0;
                const float x1 = alpha * acc[mi][nj][1] + b1;
                const float x2 = alpha * acc[mi][nj][2] + b0;
                const float x3 = alpha * acc[mi][nj][3] + b1;
                if (OUT_HALF) {
                    __half* C = reinterpret_cast<__half*>(Cv) + coff;
                    *reinterpret_cast<uint32_t*>(C + r0 * ldc + cc) = pack_h2(x0, x1);
                    *reinterpret_cast<uint32_t*>(C + r1 * ldc + cc) = pack_h2(x2, x3);
                } else {
                    float* C = reinterpret_cast<float*>(Cv) + coff;
                    *reinterpret_cast<float2*>(C + r0 * ldc + cc) = make_float2(x0, x1);
                    *reinterpret_cast<float2*>(C + r1 * ldc + cc) = make_float2(x2, x3);
                }
            }
        }
    }

    if (STATS) {
        __syncthreads();
        float* sred    = reinterpret_cast<float*>(smem);
        float* rowmaxs = reinterpret_cast<float*>(smem) + 512;

#pragma unroll
        for (int mi = 0; mi < 4; mi++) {
#pragma unroll
            for (int h = 0; h < 2; h++) {
                float mx = -1e30f;
#pragma unroll
                for (int nj = 0; nj < 4; nj++)
                    mx = fmaxf(mx, fmaxf(alpha * acc[mi][nj][h * 2],
                                         alpha * acc[mi][nj][h * 2 + 1]));
                mx = fmaxf(mx, __shfl_xor_sync(0xffffffffu, mx, 1));
                mx = fmaxf(mx, __shfl_xor_sync(0xffffffffu, mx, 2));
                const int rl = warp_m * 64 + mi * 16 + grp + h * 8;
                if (tig == 0) sred[warp_n * 128 + rl] = mx;
            }
        }
        __syncthreads();
        if (tid < 128) {
            float rm = fmaxf(fmaxf(sred[tid], sred[128 + tid]),
                             fmaxf(sred[256 + tid], sred[384 + tid]));
            rowmaxs[tid] = rm;
        }
        __syncthreads();

#pragma unroll
        for (int mi = 0; mi < 4; mi++) {
#pragma unroll
            for (int h = 0; h < 2; h++) {
                const int rl = warp_m * 64 + mi * 16 + grp + h * 8;
                const float rm = rowmaxs[rl];
                float s = 0.0f;
#pragma unroll
                for (int nj = 0; nj < 4; nj++) {
                    s += __expf(alpha * acc[mi][nj][h * 2]     - rm);
                    s += __expf(alpha * acc[mi][nj][h * 2 + 1] - rm);
                }
                s += __shfl_xor_sync(0xffffffffu, s, 1);
                s += __shfl_xor_sync(0xffffffffu, s, 2);
                if (tig == 0) sred[warp_n * 128 + rl] = s;
            }
        }
        __syncthreads();
        if (tid < 128) {
            const float sg = sred[tid] + sred[128 + tid] + sred[256 + tid] + sred[384 + tid];
            const long long gi = ((long long)z * SS + m0 + tid) * NTILE + blockIdx.x;
            statsM[gi] = rowmaxs[tid];
            statsS[gi] = sg;
        }
    }
#undef ISSUE_BODY
}

// ============================================================================
// Fused flash attention pass, 512 threads (16 warps, warp tile 32x32).
//   q persistent; k/vt double-buffered; post-ctx barrier before reissue into
//   the same buffer (R13 race fix). attn written with streaming stores.
// ============================================================================
__global__ __launch_bounds__(512, 1) void attn_flash_kernel(
    const __half* __restrict__ Qp, const __half* __restrict__ Kp,
    const __half* __restrict__ VTp, __half* __restrict__ CTX,
    float* __restrict__ ATTN,
    const float* __restrict__ rowM, const float* __restrict__ rowInv,
    float alpha)
{
    extern __shared__ char smem[];
    const uint32_t sb = smem_u32(smem);

    const int z  = blockIdx.z;
    const int zb = z >> 3;
    const int zh = z & 7;
    const int m0 = blockIdx.y * 128;

    const __half* Qg = Qp + ((long long)zb * SS + m0) * DMODEL + zh * DK;
    const __half* Kg = Kp + (long long)zb * SS * DMODEL + zh * DK;
    const __half* Vg = VTp + (long long)z * DK * SS;
    __half* Cg = CTX + ((long long)zb * SS + m0) * DMODEL + zh * DK;
    float* Ag = ATTN + ((long long)z * SS + m0) * SS;

    const int tid  = threadIdx.x;
    const int wid  = tid >> 5;         // 0..15
    const int lane = tid & 31;
    const int warp_m = wid >> 2;       // 0..3 -> 32 rows each
    const int warp_n = wid & 3;        // 0..3 -> 32 cols each
    const int grp  = lane >> 2;
    const int tig  = lane & 3;

    const int lm  = tid >> 2;          // 0..127 (full row coverage)
    const int lcw = (tid & 3) * 4;
    const int lch = (tid & 3) * 8;

    // ldmatrix prep: A warp tile 32 rows (mi 0..1); B 32 cols (pairs 0..1)
    uint32_t aBaseW[2], aXorW[2];
#pragma unroll
    for (int mi = 0; mi < 2; mi++) {
        const int rowa = warp_m * 32 + mi * 16 + (lane & 7) + ((lane >> 3) & 1) * 8;
        aBaseW[mi] = (uint32_t)rowa * 16u;
        aXorW[mi]  = (((uint32_t)rowa >> 1) & 3u) << 2;
    }
    const uint32_t aKsel = ((uint32_t)lane >> 4) * 4u;
    uint32_t bBaseW[2], bXorW[2];
#pragma unroll
    for (int p = 0; p < 2; p++) {
        const int rowb = warp_n * 32 + p * 16 + (lane & 7) + ((lane >> 4) & 1) * 8;
        bBaseW[p] = (uint32_t)rowb * 16u;
        bXorW[p]  = (((uint32_t)rowb >> 1) & 3u) << 2;
    }
    const uint32_t bKsel = (((uint32_t)lane >> 3) & 1u) * 4u;

    // per-thread row stats (rows warp_m*32 + mi*16 + grp, +8)
    float mlo[2], mhi[2], ilo[2], ihi[2];
#pragma unroll
    for (int mi = 0; mi < 2; mi++) {
        const long long r = (long long)z * SS + m0 + warp_m * 32 + mi * 16 + grp;
        mlo[mi] = rowM[r];     ilo[mi] = rowInv[r];
        mhi[mi] = rowM[r + 8]; ihi[mi] = rowInv[r + 8];
    }

    float cacc[2][4][4];
#pragma unroll
    for (int i = 0; i < 2; i++)
#pragma unroll
        for (int j = 0; j < 4; j++)
#pragma unroll
            for (int q = 0; q < 4; q++) cacc[i][j][q] = 0.0f;

    // ---- load q block (4 dk sub-tiles; 512 threads -> full tile per pass) ----
#pragma unroll
    for (int t = 0; t < 4; t++)
        cp_async16(sb + FA_Q_OFF + t * 8192u + SW_WORD(lm, lcw) * 4u,
                   Qg + (long long)lm * DMODEL + t * 32 + lch);

#define ISSUE_KV(bufi, s0)                                                      \
    {                                                                           \
        const uint32_t kb_ = sb + FA_KV_OFF + (uint32_t)(bufi) * FA_KV_STAGE;   \
        const uint32_t vb_ = kb_ + 32768u;                                      \
        _Pragma("unroll")                                                       \
        for (int t = 0; t < 4; t++) {                                           \
            cp_async16(kb_ + t * 8192u + SW_WORD(lm, lcw) * 4u,                 \
                       Kg + (long long)((s0) + lm) * DMODEL + t * 32 + lch);    \
            cp_async16(vb_ + t * 8192u + SW_WORD(lm, lcw) * 4u,                 \
                       Vg + (long long)lm * SS + (s0) + t * 32 + lch);          \
        }                                                                       \
    }

    ISSUE_KV(0, 0)    CP_COMMIT();
    ISSUE_KV(1, 128)  CP_COMMIT();

    for (int ch = 0; ch < NTILE; ch++) {
        const int s0 = ch * 128;
        const int b  = ch & 1;
        const uint32_t kbuf = sb + FA_KV_OFF + (uint32_t)b * FA_KV_STAGE;
        const uint32_t vbuf = kbuf + 32768u;

        CP_WAIT1();
        __syncthreads();

        // ---- scores tile: q @ k^T ----
        float sacc[2][4][4];
#pragma unroll
        for (int i = 0; i < 2; i++)
#pragma unroll
            for (int j = 0; j < 4; j++)
#pragma unroll
                for (int q = 0; q < 4; q++) sacc[i][j][q] = 0.0f;
#pragma unroll
        for (int t = 0; t < 4; t++) {
            const uint32_t qa = sb + FA_Q_OFF + t * 8192u;
            const uint32_t ka = kbuf + t * 8192u;
            COMPUTE_FP16_MI2(sacc, qa, ka)
        }

        // ---- transform: p = exp(alpha*s - M) * inv; stream attn; p -> smem ----
#pragma unroll
        for (int mi = 0; mi < 2; mi++) {
#pragma unroll
            for (int nj = 0; nj < 4; nj++) {
                const int cc = warp_n * 32 + nj * 8 + tig * 2;
                const float p00 = __expf(alpha * sacc[mi][nj][0] - mlo[mi]) * ilo[mi];
                const float p01 = __expf(alpha * sacc[mi][nj][1] - mlo[mi]) * ilo[mi];
                const float p10 = __expf(alpha * sacc[mi][nj][2] - mhi[mi]) * ihi[mi];
                const float p11 = __expf(alpha * sacc[mi][nj][3] - mhi[mi]) * ihi[mi];
                const int rlo = warp_m * 32 + mi * 16 + grp;
                stcs_f2(Ag + (long long)rlo * SS + s0 + cc, p00, p01);
                stcs_f2(Ag + (long long)(rlo + 8) * SS + s0 + cc, p10, p11);
                const uint32_t pw = (uint32_t)(nj * 4 + tig);
                const uint32_t poff = FA_P_OFF + (uint32_t)warp_n * 8192u;
                *reinterpret_cast<uint32_t*>(smem + poff + SW_WORD(rlo, pw) * 4u) =
                    pack_h2(p00, p01);
                *reinterpret_cast<uint32_t*>(smem + poff + SW_WORD(rlo + 8, pw) * 4u) =
                    pack_h2(p10, p11);
            }
        }
        __syncthreads();

        // ---- ctx mma: p @ vt^T ----
#pragma unroll
        for (int t = 0; t < 4; t++) {
            const uint32_t pa = sb + FA_P_OFF + t * 8192u;
            const uint32_t va = vbuf + t * 8192u;
            COMPUTE_FP16_MI2(cacc, pa, va)
        }

        // RACE FIX: all warps finish reading buffer b before reissuing into it.
        __syncthreads();

        if (ch + 2 < NTILE) {
            ISSUE_KV(b, (ch + 2) * 128)
        }
        CP_COMMIT();
    }

    // ---- write ctx fp16 ----
#pragma unroll
    for (int nj = 0; nj < 4; nj++) {
        const int cc = warp_n * 32 + nj * 8 + tig * 2;
#pragma unroll
        for (int mi = 0; mi < 2; mi++) {
            const long long r0 = warp_m * 32 + mi * 16 + grp;
            const long long r1 = r0 + 8;
            *reinterpret_cast<uint32_t*>(Cg + r0 * DMODEL + cc) =
                pack_h2(cacc[mi][nj][0], cacc[mi][nj][1]);
            *reinterpret_cast<uint32_t*>(Cg + r1 * DMODEL + cc) =
                pack_h2(cacc[mi][nj][2], cacc[mi][nj][3]);
        }
    }
#undef ISSUE_KV
}

// ============================================================================
// Prepass converters + stats combine + V transpose
// ============================================================================
__global__ __launch_bounds__(256) void cvt_weights_kernel(
    const float* __restrict__ w0, const float* __restrict__ w1,
    const float* __restrict__ w2, const float* __restrict__ w3,
    __half* __restrict__ dst)
{
    const float* src = (blockIdx.z == 0) ? w0 : (blockIdx.z == 1) ? w1
                     : (blockIdx.z == 2) ? w2 : w3;
    __half* d = dst + (size_t)blockIdx.z * DMODEL * DMODEL;
    const long long i = ((long long)blockIdx.x * 256 + threadIdx.x) * 4;
    float4 v = *reinterpret_cast<const float4*>(src + i);
    uint2 u;
    u.x = pack_h2(v.x, v.y);
    u.y = pack_h2(v.z, v.w);
    *reinterpret_cast<uint2*>(d + i) = u;
}

__global__ __launch_bounds__(256) void cvt_inputs_kernel(
    const float* __restrict__ x0, const float* __restrict__ x1,
    const float* __restrict__ x2, __half* __restrict__ dst)
{
    const float* src = (blockIdx.z == 0) ? x0 : (blockIdx.z == 1) ? x1 : x2;
    __half* d = dst + (size_t)blockIdx.z * BB * SS * DMODEL;
    const long long i = ((long long)blockIdx.x * 256 + threadIdx.x) * 4;
    float4 v = *reinterpret_cast<const float4*>(src + i);
    uint2 u;
    u.x = pack_h2(v.x, v.y);
    u.y = pack_h2(v.z, v.w);
    *reinterpret_cast<uint2*>(d + i) = u;
}

__global__ __launch_bounds__(256) void combine_stats_kernel(
    const float* __restrict__ sM, const float* __restrict__ sS,
    float* __restrict__ rowM, float* __restrict__ rowInv)
{
    const long long r = (long long)blockIdx.x * 256 + threadIdx.x;
    const float* pm = sM + r * NTILE;
    const float* ps = sS + r * NTILE;
    float M = -1e30f;
#pragma unroll
    for (int t = 0; t < NTILE; t++) M = fmaxf(M, pm[t]);
    float S = 0.0f;
#pragma unroll
    for (int t = 0; t < NTILE; t++) S += ps[t] * __expf(pm[t] - M);
    rowM[r]   = M;
    rowInv[r] = 1.0f / S;
}

__global__ void transpose_v_kernel(const __half* __restrict__ v, __half* __restrict__ vt)
{
    __shared__ __half t[32][33];
    const int z = blockIdx.z, b = z >> 3, h = z & 7;
    const int s0 = blockIdx.x * 32, n0 = blockIdx.y * 32;
    const int tx = threadIdx.x, ty = threadIdx.y;
#pragma unroll
    for (int j = ty; j < 32; j += 8)
        t[j][tx] = v[((long long)b * SS + s0 + j) * DMODEL + h * DK + n0 + tx];
    __syncthreads();
#pragma unroll
    for (int j = ty; j < 32; j += 8)
        vt[((long long)z * DK + n0 + j) * SS + s0 + tx] = t[tx][j];
}

extern "C" void kernel_launch(void* const* d_in, const int* in_sizes, int n_in,
                              void* d_out, int out_size)
{
    const float* Q  = (const float*)d_in[0];
    const float* K  = (const float*)d_in[1];
    const float* V  = (const float*)d_in[2];
    const float* Wq = (const float*)d_in[3];
    const float* bq = (const float*)d_in[4];
    const float* Wk = (const float*)d_in[5];
    const float* bk = (const float*)d_in[6];
    const float* Wv = (const float*)d_in[7];
    const float* bv = (const float*)d_in[8];
    const float* Wo = (const float*)d_in[9];
    const float* bo = (const float*)d_in[10];

    float* out = (float*)d_out;

    const long long OUT_ELEMS  = (long long)BB * SS * DMODEL;
    const long long ATTN_ELEMS = (long long)NZ * SS * SS;

    __half *qp, *kp, *vp, *vtp, *ctxp, *wp, *inp;
    float *fbp, *sMp, *sSp, *rMp, *rIp;
    cudaGetSymbolAddress((void**)&qp,   g_q);
    cudaGetSymbolAddress((void**)&kp,   g_k);
    cudaGetSymbolAddress((void**)&vp,   g_v);
    cudaGetSymbolAddress((void**)&vtp,  g_vt);
    cudaGetSymbolAddress((void**)&ctxp, g_ctx);
    cudaGetSymbolAddress((void**)&fbp,  g_attn_fb);
    cudaGetSymbolAddress((void**)&sMp,  g_statsM);
    cudaGetSymbolAddress((void**)&sSp,  g_statsS);
    cudaGetSymbolAddress((void**)&rMp,  g_rowM);
    cudaGetSymbolAddress((void**)&rIp,  g_rowInv);
    cudaGetSymbolAddress((void**)&wp,   g_w);
    cudaGetSymbolAddress((void**)&inp,  g_in);

    float* attn = ((long long)out_size >= OUT_ELEMS + ATTN_ELEMS)
                      ? (out + OUT_ELEMS) : fbp;

    // <HAS_BIAS, STATS, OUT_HALF, WRITE_C>
    auto projK  = gemm_fp16_kernel<true,  false, true,  true >;
    auto statsK = gemm_fp16_kernel<false, true,  false, false>;
    auto outK   = gemm_fp16_kernel<true,  false, false, true >;
    cudaFuncSetAttribute(projK,  cudaFuncAttributeMaxDynamicSharedMemorySize, GEMM_SMEM_BYTES);
    cudaFuncSetAttribute(statsK, cudaFuncAttributeMaxDynamicSharedMemorySize, GEMM_SMEM_BYTES);
    cudaFuncSetAttribute(outK,   cudaFuncAttributeMaxDynamicSharedMemorySize, GEMM_SMEM_BYTES);
    cudaFuncSetAttribute(attn_flash_kernel,
                         cudaFuncAttributeMaxDynamicSharedMemorySize, FA_SMEM_BYTES);

    const int M = BB * SS;
    const float inv_sqrt_dk = 0.08838834764831845f;

    dim3 blk(256);

    // 0) prepass: convert weights + inputs to fp16
    {
        dim3 gW(DMODEL * DMODEL / (256 * 4), 1, 4);
        cvt_weights_kernel<<<gW, blk>>>(Wq, Wk, Wv, Wo, wp);
        dim3 gI((BB * SS * DMODEL) / (256 * 4), 1, 3);
        cvt_inputs_kernel<<<gI, blk>>>(Q, K, V, inp);
    }
    __half* wq = wp;
    __half* wk = wp + (size_t)DMODEL * DMODEL;
    __half* wv = wp + 2 * (size_t)DMODEL * DMODEL;
    __half* wo = wp + 3 * (size_t)DMODEL * DMODEL;
    __half* qin = inp;
    __half* kin = inp + (size_t)BB * SS * DMODEL;
    __half* vin = inp + 2 * (size_t)BB * SS * DMODEL;

    // 1-3) projections
    dim3 gProj(DMODEL / 128, M / 128, 1);
    projK<<<gProj, blk, GEMM_SMEM_BYTES>>>(qin, wq, bq, qp,
        DMODEL, DMODEL, DMODEL, DMODEL, 1.0f, 1, 0, 0, 0, 0, 0, 0, nullptr, nullptr);
    projK<<<gProj, blk, GEMM_SMEM_BYTES>>>(kin, wk, bk, kp,
        DMODEL, DMODEL, DMODEL, DMODEL, 1.0f, 1, 0, 0, 0, 0, 0, 0, nullptr, nullptr);
    projK<<<gProj, blk, GEMM_SMEM_BYTES>>>(vin, wv, bv, vp,
        DMODEL, DMODEL, DMODEL, DMODEL, 1.0f, 1, 0, 0, 0, 0, 0, 0, nullptr, nullptr);

    // 3b) transpose V per head
    {
        dim3 gT(SS / 32, DK / 32, NZ);
        dim3 bT(32, 8);
        transpose_v_kernel<<<gT, bT>>>(vp, vtp);
    }

    // 4) stats pass: q @ k^T tile stats only (no score write)
    dim3 gScores(SS / 128, SS / 128, NZ);
    statsK<<<gScores, blk, GEMM_SMEM_BYTES>>>(qp, kp, nullptr, nullptr,
        DK, DMODEL, DMODEL, SS, inv_sqrt_dk,
        NHEADS,
        (long long)SS * DMODEL, (long long)DK,
        (long long)SS * DMODEL, (long long)DK,
        0, 0,
        sMp, sSp);

    // 5) combine stats
    combine_stats_kernel<<<(NZ * SS) / 256, blk>>>(sMp, sSp, rMp, rIp);

    // 6) fused flash pass (512 threads)
    {
        dim3 gF(1, SS / 128, NZ);
        attn_flash_kernel<<<gF, dim3(512), FA_SMEM_BYTES>>>(qp, kp, vtp, ctxp, attn,
                                                            rMp, rIp, inv_sqrt_dk);
    }

    // 7) out = ctx @ Wo^T + bo
    outK<<<gProj, blk, GEMM_SMEM_BYTES>>>(ctxp, wo, bo, out,
        DMODEL, DMODEL, DMODEL, DMODEL, 1.0f, 1, 0, 0, 0, 0, 0, 0, nullptr, nullptr);
}

// round 17
// speedup vs baseline: 1.0330x; 1.0330x over previous
#include <cuda_runtime.h>
#include <cuda_fp16.h>
#include <math.h>
#include <stdint.h>

#define DMODEL 1024
#define NHEADS 8
#define DK 128
#define BB 2
#define SS 2048
#define NZ (BB * NHEADS)          // 16
#define NTILE (SS / 128)          // 16

// Scratch (allocation-free rule: __device__ globals)
__device__ __half g_qkv[3][(size_t)BB * SS * DMODEL];   // q, k, v contiguous
__device__ __half g_vt[(size_t)BB * NHEADS * DK * SS];
__device__ __half g_ctx[(size_t)BB * SS * DMODEL];
__device__ float  g_attn_fb[(size_t)NZ * SS * SS];      // attn fallback only
__device__ float  g_statsM[(size_t)NZ * SS * NTILE];
__device__ float  g_statsS[(size_t)NZ * SS * NTILE];
__device__ float  g_rowM[(size_t)NZ * SS];
__device__ float  g_rowInv[(size_t)NZ * SS];
__device__ __half g_w[4][(size_t)DMODEL * DMODEL];      // wq, wk, wv, wo contiguous
__device__ __half g_in[3][(size_t)BB * SS * DMODEL];    // Q, K, V inputs contiguous

__device__ __forceinline__ uint32_t smem_u32(const void* p) {
    uint32_t a;
    asm("{ .reg .u64 t; cvta.to.shared.u64 t, %1; cvt.u32.u64 %0, t; }" : "=r"(a) : "l"(p));
    return a;
}
__device__ __forceinline__ void mma_fp16(float* c, const uint32_t* a, const uint32_t* b) {
    asm volatile(
        "mma.sync.aligned.m16n8k16.row.col.f32.f16.f16.f32 "
        "{%0,%1,%2,%3},{%4,%5,%6,%7},{%8,%9},{%0,%1,%2,%3};"
        : "+f"(c[0]), "+f"(c[1]), "+f"(c[2]), "+f"(c[3])
        : "r"(a[0]), "r"(a[1]), "r"(a[2]), "r"(a[3]), "r"(b[0]), "r"(b[1]));
}
__device__ __forceinline__ void ldmatrix_x4(uint32_t* r, uint32_t addr) {
    asm volatile("ldmatrix.sync.aligned.m8n8.x4.shared.b16 {%0,%1,%2,%3}, [%4];"
                 : "=r"(r[0]), "=r"(r[1]), "=r"(r[2]), "=r"(r[3]) : "r"(addr));
}
__device__ __forceinline__ void cp_async16(uint32_t saddr, const void* gaddr) {
    asm volatile("cp.async.cg.shared.global [%0], [%1], 16;"
                 :: "r"(saddr), "l"(gaddr) : "memory");
}
#define CP_COMMIT() asm volatile("cp.async.commit_group;" ::: "memory")
#define CP_WAIT1()  asm volatile("cp.async.wait_group 1;" ::: "memory")

__device__ __forceinline__ uint32_t pack_h2(float lo, float hi) {
    __half2 h = __floats2half2_rn(lo, hi);
    return *reinterpret_cast<uint32_t*>(&h);
}
__device__ __forceinline__ void stcs_f2(float* p, float x, float y) {
    asm volatile("st.global.cs.v2.f32 [%0], {%1, %2};" :: "l"(p), "f"(x), "f"(y) : "memory");
}

// smem word index for (row m, k-word k) within a [rows x 32-half] sub-tile.
#define SW_WORD(m, k) ((uint32_t)(m) * 16u + ((uint32_t)(k) ^ (((((uint32_t)(m)) >> 1) & 3u) << 2)))

#define STAGE_BYTES 16384u        // A(8KB) + B(8KB) per 32-half stage
#define GEMM_SMEM_BYTES 98304u    // 6 stages = 3 pair-groups

// fused attention smem layout
#define FA_Q_OFF  0u              // 4 sub-tiles (dk)      32KB
#define FA_P_OFF  32768u          // 4 sub-tiles (s-local) 32KB
#define FA_KV_OFF 65536u          // stage b: k 32KB + vt 32KB
#define FA_KV_STAGE 65536u
#define FA_SMEM_BYTES (65536u + 2u * FA_KV_STAGE)   // 196608

// ldmatrix address prep (f16 m16n8k16), warp tile 64x32 (mi 0..3)
#define LDM_PREP()                                                              \
    uint32_t aBaseW[4], aXorW[4];                                               \
    _Pragma("unroll")                                                           \
    for (int mi = 0; mi < 4; mi++) {                                            \
        const int rowa = warp_m * 64 + mi * 16 + (lane & 7) + ((lane >> 3) & 1) * 8; \
        aBaseW[mi] = (uint32_t)rowa * 16u;                                      \
        aXorW[mi]  = (((uint32_t)rowa >> 1) & 3u) << 2;                         \
    }                                                                           \
    const uint32_t aKsel = ((uint32_t)lane >> 4) * 4u;                          \
    uint32_t bBaseW[2], bXorW[2];                                               \
    _Pragma("unroll")                                                           \
    for (int p = 0; p < 2; p++) {                                               \
        const int rowb = warp_n * 32 + p * 16 + (lane & 7) + ((lane >> 4) & 1) * 8; \
        bBaseW[p] = (uint32_t)rowb * 16u;                                       \
        bXorW[p]  = (((uint32_t)rowb >> 1) & 3u) << 2;                          \
    }                                                                           \
    const uint32_t bKsel = (((uint32_t)lane >> 3) & 1u) * 4u;

// 2 x k16 mma steps over one 32-half sub-tile pair, into named accumulator.
#define COMPUTE_FP16(accN, abufAddr, bbufAddr)                                  \
    {                                                                           \
        _Pragma("unroll")                                                       \
        for (int ks = 0; ks < 2; ks++) {                                        \
            const uint32_t kb = ks * 8;                                         \
            uint32_t af[4][4], bf[2][4];                                        \
            _Pragma("unroll")                                                   \
            for (int mi = 0; mi < 4; mi++) {                                    \
                const uint32_t kw = kb + aKsel;                                 \
                ldmatrix_x4(af[mi], (abufAddr) + (aBaseW[mi] + (kw ^ aXorW[mi])) * 4u); \
            }                                                                   \
            _Pragma("unroll")                                                   \
            for (int p = 0; p < 2; p++) {                                       \
                const uint32_t kw = kb + bKsel;                                 \
                ldmatrix_x4(bf[p], (bbufAddr) + (bBaseW[p] + (kw ^ bXorW[p])) * 4u); \
            }                                                                   \
            _Pragma("unroll")                                                   \
            for (int mi = 0; mi < 4; mi++)                                      \
                _Pragma("unroll")                                               \
                for (int nj = 0; nj < 4; nj++)                                  \
                    mma_fp16(accN[mi][nj], af[mi], &bf[nj >> 1][(nj & 1) * 2]); \
        }                                                                       \
    }

// ============================================================================
// Batched FP16 GEMM, pair-grouped cp.async pipeline. 256 threads, 2 CTA/SM.
//   C = alpha * A @ B^T + bias.  WRITE_C=false: stats-only.  K%64==0, K>=128.
//   MULTI_BIAS: bias selected per-z from {bias, bias1, bias2} (fused QKV).
// ============================================================================
template <bool HAS_BIAS, bool STATS, bool OUT_HALF, bool WRITE_C, bool MULTI_BIAS>
__global__ __launch_bounds__(256, 2) void gemm_fp16_kernel(
    const __half* __restrict__ A, const __half* __restrict__ B,
    const float* __restrict__ bias, void* __restrict__ Cv,
    int K, int lda, int ldb, int ldc, float alpha,
    int Hdiv,
    long long sAb, long long sAh,
    long long sBb, long long sBh,
    long long sCb, long long sCh,
    float* __restrict__ statsM, float* __restrict__ statsS,
    const float* __restrict__ bias1, const float* __restrict__ bias2)
{
    extern __shared__ char smem[];
    const uint32_t sb = smem_u32(smem);

    const int z  = blockIdx.z;
    const int zb = z / Hdiv;
    const int zh = z % Hdiv;
    A += zb * sAb + zh * sAh;
    B += zb * sBb + zh * sBh;
    const long long coff = zb * sCb + zh * sCh;

    const float* bp = bias;
    if (MULTI_BIAS) bp = (z == 0) ? bias : (z == 1) ? bias1 : bias2;

    const int tid  = threadIdx.x;
    const int wid  = tid >> 5;
    const int lane = tid & 31;
    const int m0   = blockIdx.y * 128;
    const int n0   = blockIdx.x * 128;
    const int warp_m = wid >> 2;
    const int warp_n = wid & 3;
    const int grp  = lane >> 2;
    const int tig  = lane & 3;

    const int lm  = tid >> 2;
    const int lcw = (tid & 3) * 4;
    const int lch = (tid & 3) * 8;

    LDM_PREP()

    float acc[4][4][4];
#pragma unroll
    for (int i = 0; i < 4; i++)
#pragma unroll
        for (int j = 0; j < 4; j++)
#pragma unroll
            for (int q = 0; q < 4; q++) acc[i][j][q] = 0.0f;

#define ISSUE_BODY(bufi, k0)                                                    \
    {                                                                           \
        const uint32_t ab = sb + (uint32_t)(bufi) * STAGE_BYTES;                \
        const uint32_t bbs = ab + 8192u;                                        \
        _Pragma("unroll")                                                       \
        for (int i = 0; i < 2; i++) {                                           \
            const int m = lm + i * 64;                                          \
            cp_async16(ab + SW_WORD(m, lcw) * 4u,                               \
                       A + (long long)(m0 + m) * lda + (k0) + lch);             \
            cp_async16(bbs + SW_WORD(m, lcw) * 4u,                              \
                       B + (long long)(n0 + m) * ldb + (k0) + lch);             \
        }                                                                       \
    }

    const int G = K >> 6;   // pair-groups of 64 halves

    ISSUE_BODY(0, 0)
    ISSUE_BODY(1, 32)
    CP_COMMIT();
    ISSUE_BODY(2, 64)
    ISSUE_BODY(3, 96)
    CP_COMMIT();

    for (int g = 0; g < G; g++) {
        CP_WAIT1();
        __syncthreads();
        const int pb = (g % 3) * 2;
        {
            const uint32_t a0 = sb + (uint32_t)pb * STAGE_BYTES;
            COMPUTE_FP16(acc, a0, a0 + 8192u)
            const uint32_t a1 = a0 + STAGE_BYTES;
            COMPUTE_FP16(acc, a1, a1 + 8192u)
        }
        if (g + 2 < G) {
            const int tb = ((g + 2) % 3) * 2;
            ISSUE_BODY(tb,     (g + 2) * 64)
            ISSUE_BODY(tb + 1, (g + 2) * 64 + 32)
        }
        CP_COMMIT();
    }

    if (WRITE_C) {
#pragma unroll
        for (int nj = 0; nj < 4; nj++) {
            const int cc = n0 + warp_n * 32 + nj * 8 + tig * 2;
            float b0 = 0.0f, b1 = 0.0f;
            if (HAS_BIAS) { b0 = bp[cc]; b1 = bp[cc + 1]; }
#pragma unroll
            for (int mi = 0; mi < 4; mi++) {
                const long long r0 = m0 + warp_m * 64 + mi * 16 + grp;
                const long long r1 = r0 + 8;
                const float x0 = alpha * acc[mi][nj][0] + b0;
                const float x1 = alpha * acc[mi][nj][1] + b1;
                const float x2 = alpha * acc[mi][nj][2] + b0;
                const float x3 = alpha * acc[mi][nj][3] + b1;
                if (OUT_HALF) {
                    __half* C = reinterpret_cast<__half*>(Cv) + coff;
                    *reinterpret_cast<uint32_t*>(C + r0 * ldc + cc) = pack_h2(x0, x1);
                    *reinterpret_cast<uint32_t*>(C + r1 * ldc + cc) = pack_h2(x2, x3);
                } else {
                    float* C = reinterpret_cast<float*>(Cv) + coff;
                    *reinterpret_cast<float2*>(C + r0 * ldc + cc) = make_float2(x0, x1);
                    *reinterpret_cast<float2*>(C + r1 * ldc + cc) = make_float2(x2, x3);
                }
            }
        }
    }

    if (STATS) {
        __syncthreads();
        float* sred    = reinterpret_cast<float*>(smem);
        float* rowmaxs = reinterpret_cast<float*>(smem) + 512;

#pragma unroll
        for (int mi = 0; mi < 4; mi++) {
#pragma unroll
            for (int h = 0; h < 2; h++) {
                float mx = -1e30f;
#pragma unroll
                for (int nj = 0; nj < 4; nj++)
                    mx = fmaxf(mx, fmaxf(alpha * acc[mi][nj][h * 2],
                                         alpha * acc[mi][nj][h * 2 + 1]));
                mx = fmaxf(mx, __shfl_xor_sync(0xffffffffu, mx, 1));
                mx = fmaxf(mx, __shfl_xor_sync(0xffffffffu, mx, 2));
                const int rl = warp_m * 64 + mi * 16 + grp + h * 8;
                if (tig == 0) sred[warp_n * 128 + rl] = mx;
            }
        }
        __syncthreads();
        if (tid < 128) {
            float rm = fmaxf(fmaxf(sred[tid], sred[128 + tid]),
                             fmaxf(sred[256 + tid], sred[384 + tid]));
            rowmaxs[tid] = rm;
        }
        __syncthreads();

#pragma unroll
        for (int mi = 0; mi < 4; mi++) {
#pragma unroll
            for (int h = 0; h < 2; h++) {
                const int rl = warp_m * 64 + mi * 16 + grp + h * 8;
                const float rm = rowmaxs[rl];
                float s = 0.0f;
#pragma unroll
                for (int nj = 0; nj < 4; nj++) {
                    s += __expf(alpha * acc[mi][nj][h * 2]     - rm);
                    s += __expf(alpha * acc[mi][nj][h * 2 + 1] - rm);
                }
                s += __shfl_xor_sync(0xffffffffu, s, 1);
                s += __shfl_xor_sync(0xffffffffu, s, 2);
                if (tig == 0) sred[warp_n * 128 + rl] = s;
            }
        }
        __syncthreads();
        if (tid < 128) {
            const float sg = sred[tid] + sred[128 + tid] + sred[256 + tid] + sred[384 + tid];
            const long long gi = ((long long)z * SS + m0 + tid) * NTILE + blockIdx.x;
            statsM[gi] = rowmaxs[tid];
            statsS[gi] = sg;
        }
    }
#undef ISSUE_BODY
}

// ============================================================================
// Fused flash attention pass (R15 proven config: 256 threads, warp tile 64x32).
// ============================================================================
__global__ __launch_bounds__(256, 1) void attn_flash_kernel(
    const __half* __restrict__ Qp, const __half* __restrict__ Kp,
    const __half* __restrict__ VTp, __half* __restrict__ CTX,
    float* __restrict__ ATTN,
    const float* __restrict__ rowM, const float* __restrict__ rowInv,
    float alpha)
{
    extern __shared__ char smem[];
    const uint32_t sb = smem_u32(smem);

    const int z  = blockIdx.z;
    const int zb = z >> 3;
    const int zh = z & 7;
    const int m0 = blockIdx.y * 128;

    const __half* Qg = Qp + ((long long)zb * SS + m0) * DMODEL + zh * DK;
    const __half* Kg = Kp + (long long)zb * SS * DMODEL + zh * DK;
    const __half* Vg = VTp + (long long)z * DK * SS;
    __half* Cg = CTX + ((long long)zb * SS + m0) * DMODEL + zh * DK;
    float* Ag = ATTN + ((long long)z * SS + m0) * SS;

    const int tid  = threadIdx.x;
    const int wid  = tid >> 5;
    const int lane = tid & 31;
    const int warp_m = wid >> 2;
    const int warp_n = wid & 3;
    const int grp  = lane >> 2;
    const int tig  = lane & 3;

    const int lm  = tid >> 2;
    const int lcw = (tid & 3) * 4;
    const int lch = (tid & 3) * 8;

    LDM_PREP()

    float mlo[4], mhi[4], ilo[4], ihi[4];
#pragma unroll
    for (int mi = 0; mi < 4; mi++) {
        const long long r = (long long)z * SS + m0 + warp_m * 64 + mi * 16 + grp;
        mlo[mi] = rowM[r];     ilo[mi] = rowInv[r];
        mhi[mi] = rowM[r + 8]; ihi[mi] = rowInv[r + 8];
    }

    float cacc[4][4][4];
#pragma unroll
    for (int i = 0; i < 4; i++)
#pragma unroll
        for (int j = 0; j < 4; j++)
#pragma unroll
            for (int q = 0; q < 4; q++) cacc[i][j][q] = 0.0f;

    // ---- load q block (4 dk sub-tiles) ----
#pragma unroll
    for (int t = 0; t < 4; t++)
#pragma unroll
        for (int i = 0; i < 2; i++) {
            const int m = lm + i * 64;
            cp_async16(sb + FA_Q_OFF + t * 8192u + SW_WORD(m, lcw) * 4u,
                       Qg + (long long)m * DMODEL + t * 32 + lch);
        }

#define ISSUE_KV(bufi, s0)                                                      \
    {                                                                           \
        const uint32_t kb_ = sb + FA_KV_OFF + (uint32_t)(bufi) * FA_KV_STAGE;   \
        const uint32_t vb_ = kb_ + 32768u;                                      \
        _Pragma("unroll")                                                       \
        for (int t = 0; t < 4; t++)                                             \
            _Pragma("unroll")                                                   \
            for (int i = 0; i < 2; i++) {                                       \
                const int m = lm + i * 64;                                      \
                cp_async16(kb_ + t * 8192u + SW_WORD(m, lcw) * 4u,              \
                           Kg + (long long)((s0) + m) * DMODEL + t * 32 + lch); \
                cp_async16(vb_ + t * 8192u + SW_WORD(m, lcw) * 4u,              \
                           Vg + (long long)m * SS + (s0) + t * 32 + lch);       \
            }                                                                   \
    }

    ISSUE_KV(0, 0)    CP_COMMIT();
    ISSUE_KV(1, 128)  CP_COMMIT();

    for (int ch = 0; ch < NTILE; ch++) {
        const int s0 = ch * 128;
        const int b  = ch & 1;
        const uint32_t kbuf = sb + FA_KV_OFF + (uint32_t)b * FA_KV_STAGE;
        const uint32_t vbuf = kbuf + 32768u;

        CP_WAIT1();
        __syncthreads();

        // ---- scores tile: q @ k^T ----
        float sacc[4][4][4];
#pragma unroll
        for (int i = 0; i < 4; i++)
#pragma unroll
            for (int j = 0; j < 4; j++)
#pragma unroll
                for (int q = 0; q < 4; q++) sacc[i][j][q] = 0.0f;
#pragma unroll
        for (int t = 0; t < 4; t++) {
            const uint32_t qa = sb + FA_Q_OFF + t * 8192u;
            const uint32_t ka = kbuf + t * 8192u;
            COMPUTE_FP16(sacc, qa, ka)
        }

        // ---- transform: p = exp(alpha*s - M) * inv; stream attn; p -> smem ----
#pragma unroll
        for (int mi = 0; mi < 4; mi++) {
#pragma unroll
            for (int nj = 0; nj < 4; nj++) {
                const int cc = warp_n * 32 + nj * 8 + tig * 2;
                const float p00 = __expf(alpha * sacc[mi][nj][0] - mlo[mi]) * ilo[mi];
                const float p01 = __expf(alpha * sacc[mi][nj][1] - mlo[mi]) * ilo[mi];
                const float p10 = __expf(alpha * sacc[mi][nj][2] - mhi[mi]) * ihi[mi];
                const float p11 = __expf(alpha * sacc[mi][nj][3] - mhi[mi]) * ihi[mi];
                const int rlo = warp_m * 64 + mi * 16 + grp;
                stcs_f2(Ag + (long long)rlo * SS + s0 + cc, p00, p01);
                stcs_f2(Ag + (long long)(rlo + 8) * SS + s0 + cc, p10, p11);
                const uint32_t pw = (uint32_t)(nj * 4 + tig);
                const uint32_t poff = FA_P_OFF + (uint32_t)warp_n * 8192u;
                *reinterpret_cast<uint32_t*>(smem + poff + SW_WORD(rlo, pw) * 4u) =
                    pack_h2(p00, p01);
                *reinterpret_cast<uint32_t*>(smem + poff + SW_WORD(rlo + 8, pw) * 4u) =
                    pack_h2(p10, p11);
            }
        }
        __syncthreads();

        // ---- ctx mma: p @ vt^T ----
#pragma unroll
        for (int t = 0; t < 4; t++) {
            const uint32_t pa = sb + FA_P_OFF + t * 8192u;
            const uint32_t va = vbuf + t * 8192u;
            COMPUTE_FP16(cacc, pa, va)
        }

        // RACE FIX: all warps finish reading buffer b before reissuing into it.
        __syncthreads();

        if (ch + 2 < NTILE) {
            ISSUE_KV(b, (ch + 2) * 128)
        }
        CP_COMMIT();
    }

    // ---- write ctx fp16 ----
#pragma unroll
    for (int nj = 0; nj < 4; nj++) {
        const int cc = warp_n * 32 + nj * 8 + tig * 2;
#pragma unroll
        for (int mi = 0; mi < 4; mi++) {
            const long long r0 = warp_m * 64 + mi * 16 + grp;
            const long long r1 = r0 + 8;
            *reinterpret_cast<uint32_t*>(Cg + r0 * DMODEL + cc) =
                pack_h2(cacc[mi][nj][0], cacc[mi][nj][1]);
            *reinterpret_cast<uint32_t*>(Cg + r1 * DMODEL + cc) =
                pack_h2(cacc[mi][nj][2], cacc[mi][nj][3]);
        }
    }
#undef ISSUE_KV
}

// ============================================================================
// Prepass converters + stats combine + V transpose
// ============================================================================
__global__ __launch_bounds__(256) void cvt_weights_kernel(
    const float* __restrict__ w0, const float* __restrict__ w1,
    const float* __restrict__ w2, const float* __restrict__ w3,
    __half* __restrict__ dst)
{
    const float* src = (blockIdx.z == 0) ? w0 : (blockIdx.z == 1) ? w1
                     : (blockIdx.z == 2) ? w2 : w3;
    __half* d = dst + (size_t)blockIdx.z * DMODEL * DMODEL;
    const long long i = ((long long)blockIdx.x * 256 + threadIdx.x) * 4;
    float4 v = *reinterpret_cast<const float4*>(src + i);
    uint2 u;
    u.x = pack_h2(v.x, v.y);
    u.y = pack_h2(v.z, v.w);
    *reinterpret_cast<uint2*>(d + i) = u;
}

__global__ __launch_bounds__(256) void cvt_inputs_kernel(
    const float* __restrict__ x0, const float* __restrict__ x1,
    const float* __restrict__ x2, __half* __restrict__ dst)
{
    const float* src = (blockIdx.z == 0) ? x0 : (blockIdx.z == 1) ? x1 : x2;
    __half* d = dst + (size_t)blockIdx.z * BB * SS * DMODEL;
    const long long i = ((long long)blockIdx.x * 256 + threadIdx.x) * 4;
    float4 v = *reinterpret_cast<const float4*>(src + i);
    uint2 u;
    u.x = pack_h2(v.x, v.y);
    u.y = pack_h2(v.z, v.w);
    *reinterpret_cast<uint2*>(d + i) = u;
}

__global__ __launch_bounds__(256) void combine_stats_kernel(
    const float* __restrict__ sM, const float* __restrict__ sS,
    float* __restrict__ rowM, float* __restrict__ rowInv)
{
    const long long r = (long long)blockIdx.x * 256 + threadIdx.x;
    const float* pm = sM + r * NTILE;
    const float* ps = sS + r * NTILE;
    float M = -1e30f;
#pragma unroll
    for (int t = 0; t < NTILE; t++) M = fmaxf(M, pm[t]);
    float S = 0.0f;
#pragma unroll
    for (int t = 0; t < NTILE; t++) S += ps[t] * __expf(pm[t] - M);
    rowM[r]   = M;
    rowInv[r] = 1.0f / S;
}

__global__ void transpose_v_kernel(const __half* __restrict__ v, __half* __restrict__ vt)
{
    __shared__ __half t[32][33];
    const int z = blockIdx.z, b = z >> 3, h = z & 7;
    const int s0 = blockIdx.x * 32, n0 = blockIdx.y * 32;
    const int tx = threadIdx.x, ty = threadIdx.y;
#pragma unroll
    for (int j = ty; j < 32; j += 8)
        t[j][tx] = v[((long long)b * SS + s0 + j) * DMODEL + h * DK + n0 + tx];
    __syncthreads();
#pragma unroll
    for (int j = ty; j < 32; j += 8)
        vt[((long long)z * DK + n0 + j) * SS + s0 + tx] = t[tx][j];
}

extern "C" void kernel_launch(void* const* d_in, const int* in_sizes, int n_in,
                              void* d_out, int out_size)
{
    const float* Q  = (const float*)d_in[0];
    const float* K  = (const float*)d_in[1];
    const float* V  = (const float*)d_in[2];
    const float* Wq = (const float*)d_in[3];
    const float* bq = (const float*)d_in[4];
    const float* Wk = (const float*)d_in[5];
    const float* bk = (const float*)d_in[6];
    const float* Wv = (const float*)d_in[7];
    const float* bv = (const float*)d_in[8];
    const float* Wo = (const float*)d_in[9];
    const float* bo = (const float*)d_in[10];

    float* out = (float*)d_out;

    const long long OUT_ELEMS  = (long long)BB * SS * DMODEL;
    const long long ATTN_ELEMS = (long long)NZ * SS * SS;
    const long long IN_STRIDE  = (long long)BB * SS * DMODEL;   // halves

    __half *qkvp, *vtp, *ctxp, *wp, *inp;
    float *fbp, *sMp, *sSp, *rMp, *rIp;
    cudaGetSymbolAddress((void**)&qkvp, g_qkv);
    cudaGetSymbolAddress((void**)&vtp,  g_vt);
    cudaGetSymbolAddress((void**)&ctxp, g_ctx);
    cudaGetSymbolAddress((void**)&fbp,  g_attn_fb);
    cudaGetSymbolAddress((void**)&sMp,  g_statsM);
    cudaGetSymbolAddress((void**)&sSp,  g_statsS);
    cudaGetSymbolAddress((void**)&rMp,  g_rowM);
    cudaGetSymbolAddress((void**)&rIp,  g_rowInv);
    cudaGetSymbolAddress((void**)&wp,   g_w);
    cudaGetSymbolAddress((void**)&inp,  g_in);

    __half* qp = qkvp;
    __half* kp = qkvp + IN_STRIDE;
    __half* vp = qkvp + 2 * IN_STRIDE;

    float* attn = ((long long)out_size >= OUT_ELEMS + ATTN_ELEMS)
                      ? (out + OUT_ELEMS) : fbp;

    // <HAS_BIAS, STATS, OUT_HALF, WRITE_C, MULTI_BIAS>
    auto projK  = gemm_fp16_kernel<true,  false, true,  true,  true >;
    auto statsK = gemm_fp16_kernel<false, true,  false, false, false>;
    auto outK   = gemm_fp16_kernel<true,  false, false, true,  false>;
    cudaFuncSetAttribute(projK,  cudaFuncAttributeMaxDynamicSharedMemorySize, GEMM_SMEM_BYTES);
    cudaFuncSetAttribute(statsK, cudaFuncAttributeMaxDynamicSharedMemorySize, GEMM_SMEM_BYTES);
    cudaFuncSetAttribute(outK,   cudaFuncAttributeMaxDynamicSharedMemorySize, GEMM_SMEM_BYTES);
    cudaFuncSetAttribute(attn_flash_kernel,
                         cudaFuncAttributeMaxDynamicSharedMemorySize, FA_SMEM_BYTES);

    const int M = BB * SS;
    const float inv_sqrt_dk = 0.08838834764831845f;

    dim3 blk(256);

    // 0) prepass: convert weights + inputs to fp16
    {
        dim3 gW(DMODEL * DMODEL / (256 * 4), 1, 4);
        cvt_weights_kernel<<<gW, blk>>>(Wq, Wk, Wv, Wo, wp);
        dim3 gI((BB * SS * DMODEL) / (256 * 4), 1, 3);
        cvt_inputs_kernel<<<gI, blk>>>(Q, K, V, inp);
    }
    __half* wo = wp + 3 * (size_t)DMODEL * DMODEL;

    // 1) fused QKV projections: one launch, grid.z = 3 (q, k, v)
    {
        dim3 gProj3(DMODEL / 128, M / 128, 3);
        projK<<<gProj3, blk, GEMM_SMEM_BYTES>>>(inp, wp, bq, qkvp,
            DMODEL, DMODEL, DMODEL, DMODEL, 1.0f,
            1,
            IN_STRIDE, 0,
            (long long)DMODEL * DMODEL, 0,
            IN_STRIDE, 0,
            nullptr, nullptr, bk, bv);
    }

    // 3b) transpose V per head
    {
        dim3 gT(SS / 32, DK / 32, NZ);
        dim3 bT(32, 8);
        transpose_v_kernel<<<gT, bT>>>(vp, vtp);
    }

    // 4) stats pass: q @ k^T tile stats only (no score write)
    dim3 gScores(SS / 128, SS / 128, NZ);
    statsK<<<gScores, blk, GEMM_SMEM_BYTES>>>(qp, kp, nullptr, nullptr,
        DK, DMODEL, DMODEL, SS, inv_sqrt_dk,
        NHEADS,
        (long long)SS * DMODEL, (long long)DK,
        (long long)SS * DMODEL, (long long)DK,
        0, 0,
        sMp, sSp, nullptr, nullptr);

    // 5) combine stats
    combine_stats_kernel<<<(NZ * SS) / 256, blk>>>(sMp, sSp, rMp, rIp);

    // 6) fused flash pass (256 threads — R15 proven config)
    {
        dim3 gF(1, SS / 128, NZ);
        attn_flash_kernel<<<gF, blk, FA_SMEM_BYTES>>>(qp, kp, vtp, ctxp, attn,
                                                      rMp, rIp, inv_sqrt_dk);
    }

    // 7) out = ctx @ Wo^T + bo
    {
        dim3 gProj(DMODEL / 128, M / 128, 1);
        outK<<<gProj, blk, GEMM_SMEM_BYTES>>>(ctxp, wo, bo, out,
            DMODEL, DMODEL, DMODEL, DMODEL, 1.0f,
            1, 0, 0, 0, 0, 0, 0, nullptr, nullptr, nullptr, nullptr);
    }
}